// round 9
// baseline (speedup 1.0000x reference)
#include <cuda_runtime.h>
#include <cstdint>

// Problem shape (fixed by the reference)
#define B_DIM 16
#define S_DIM 4096
#define D_DIM 1024
#define D_VEC (D_DIM / 4)            // 256 float4 per weight row
#define WARPS_PER_CTA 2
#define THREADS_PER_CTA (WARPS_PER_CTA * 32)              // 64
#define TOKENS_PER_WARP 2
#define ITERS 4
#define TOKENS_PER_CTA (WARPS_PER_CTA * TOKENS_PER_WARP * ITERS)   // 16

__global__ void zero_out_kernel(float* __restrict__ out, int n) {
    int i = blockIdx.x * blockDim.x + threadIdx.x;
    if (i < n) out[i] = 0.0f;
}

__device__ __forceinline__ float warp_sum(float v) {
    #pragma unroll
    for (int off = 16; off > 0; off >>= 1)
        v += __shfl_xor_sync(0xFFFFFFFFu, v, off);
    return v;
}

__global__ __launch_bounds__(THREADS_PER_CTA, 16)   // <=64 regs, 16 CTAs/SM
void icreward_kernel(const float*  __restrict__ x,       // (B,S,D)
                     const float*  __restrict__ W,       // (2,D)
                     const float*  __restrict__ bias,    // (2,)
                     const int*    __restrict__ lengths, // (B,)
                     float*        __restrict__ out)     // (B,)
{
    const int b   = blockIdx.y;
    const int len = lengths[b];
    const int s0  = blockIdx.x * TOKENS_PER_CTA;

    // Fine-grained early exit: 16-token quantum (load-balance + traffic win)
    if (s0 >= len) return;

    __shared__ float4 w0s[D_VEC];
    __shared__ float4 w1s[D_VEC];
    __shared__ float  warp_sums[WARPS_PER_CTA];

    const int tid  = threadIdx.x;
    const int wid  = tid >> 5;
    const int lane = tid & 31;

    // Scalars first so they aren't queued behind the streaming loads
    const float b0v = bias[0];
    const float b1v = bias[1];

    // Stage W into shared: 64 threads x 4 float4 per row
    {
        const float4* W0 = reinterpret_cast<const float4*>(W);
        const float4* W1 = reinterpret_cast<const float4*>(W + D_DIM);
        #pragma unroll
        for (int k = 0; k < 4; ++k) {
            w0s[tid + 64 * k] = W0[tid + 64 * k];
            w1s[tid + 64 * k] = W1[tid + 64 * k];
        }
    }
    __syncthreads();

    const float* xb = x + (size_t)b * S_DIM * D_DIM;

    float wsum = 0.0f;   // meaningful on lane 0 only

    // Warp w owns tokens [s0 + w*8, s0 + w*8 + 8), processed 2 at a time
    const int wbase = s0 + wid * (TOKENS_PER_WARP * ITERS);

    #pragma unroll
    for (int it = 0; it < ITERS; ++it) {
        const int sbase = wbase + it * TOKENS_PER_WARP;
        if (sbase >= len) break;

        const float4* r = reinterpret_cast<const float4*>(xb + (size_t)sbase * D_DIM);
        const bool v1 = (sbase + 1) < len;

        float a00 = 0.f, a10 = 0.f;   // token 0: dot(w0), dot(w1)
        float a01 = 0.f, a11 = 0.f;   // token 1

        #pragma unroll
        for (int k = 0; k < 8; ++k) {
            const int idx = lane + k * 32;            // coalesced across lanes
            const float4 w0 = w0s[idx];
            const float4 w1 = w1s[idx];

            {
                float4 xv = __ldcs(&r[idx]);          // streaming, evict-first
                a00 += xv.x * w0.x + xv.y * w0.y + xv.z * w0.z + xv.w * w0.w;
                a10 += xv.x * w1.x + xv.y * w1.y + xv.z * w1.z + xv.w * w1.w;
            }
            if (v1) {
                float4 xv = __ldcs(&r[idx + D_VEC]);  // next token, +4KB
                a01 += xv.x * w0.x + xv.y * w0.y + xv.z * w0.z + xv.w * w0.w;
                a11 += xv.x * w1.x + xv.y * w1.y + xv.z * w1.z + xv.w * w1.w;
            }
        }

        a00 = warp_sum(a00);  a10 = warp_sum(a10);
        a01 = warp_sum(a01);  a11 = warp_sum(a11);

        if (lane == 0) {
            {
                float g = 1.0f / (1.0f + __expf(-(a00 + b0v)));
                wsum += g * (a10 + b1v);
            }
            if (v1) {
                float g = 1.0f / (1.0f + __expf(-(a01 + b0v)));
                wsum += g * (a11 + b1v);
            }
        }
    }

    if (lane == 0) warp_sums[wid] = wsum;
    __syncthreads();

    if (tid == 0) {
        atomicAdd(&out[b], warp_sums[0] + warp_sums[1]);
    }
}

extern "C" void kernel_launch(void* const* d_in, const int* in_sizes, int n_in,
                              void* d_out, int out_size) {
    const float* x       = (const float*)d_in[0];  // (B,S,D) fp32
    const float* W       = (const float*)d_in[1];  // (2,D)   fp32
    const float* bias    = (const float*)d_in[2];  // (2,)    fp32
    const int*   lengths = (const int*)d_in[3];    // (B,)    int32
    float*       out     = (float*)d_out;          // (B,)    fp32

    zero_out_kernel<<<1, 32>>>(out, out_size);

    dim3 grid(S_DIM / TOKENS_PER_CTA, B_DIM);      // (256, 16)
    icreward_kernel<<<grid, THREADS_PER_CTA>>>(x, W, bias, lengths, out);
}